// round 13
// baseline (speedup 1.0000x reference)
#include <cuda_runtime.h>
#include <math_constants.h>

#define BB 32
#define CC 1024
#define HW 784
#define NF4 196          // HW/4
#define REDU 64
#define TD 768
#define AD 256
#define NCH 16           // chunks for contraction: 64 channels each
#define NCHC 64          // CC/NCH
#define NB 888           // 6 blocks/SM * 148 SMs (resident @ 42 regs)
#define NSW 840          // sweep blocks in P0; [840,888) = side work

// ---- scratch (device globals; no allocation allowed) ----
__device__ float d_avg[BB*CC];
__device__ float d_maxv[BB*CC];
__device__ float d_chattn[BB*CC];
__device__ float d_qk[BB*CC];
__device__ float d_hs[BB*REDU];
__device__ float d_q[BB*AD];
__device__ float d_u[CC];
__device__ float d_pS[BB*NCH*HW];
__device__ float d_pY[BB*NCH*HW];
__device__ float d_s[BB];
__device__ unsigned int g_cnt[4];
__device__ volatile unsigned int g_gen[4];

__device__ __forceinline__ float warp_sum(float v){
  #pragma unroll
  for (int o=16;o;o>>=1) v += __shfl_xor_sync(0xffffffffu, v, o);
  return v;
}
__device__ __forceinline__ float warp_max(float v){
  #pragma unroll
  for (int o=16;o;o>>=1) v = fmaxf(v, __shfl_xor_sync(0xffffffffu, v, o));
  return v;
}

// producer-gated phase gates: producers arrive, consumers spin on gen flip.
__device__ __forceinline__ void arrive_gate(int i, unsigned int tgt){
  __threadfence();
  __syncthreads();
  if (threadIdx.x==0){
    if (atomicAdd(&g_cnt[i],1u) == tgt-1u){
      g_cnt[i] = 0u;
      __threadfence();
      g_gen[i] = g_gen[i] + 1u;   // release
    }
  }
}
__device__ __forceinline__ void wait_gate(int i, unsigned int base){
  if (threadIdx.x==0){
    while (g_gen[i] == base) {}   // volatile spin
    __threadfence();              // acquire
  }
  __syncthreads();
}

__global__ void __launch_bounds__(256, 6)
mega(const float* __restrict__ x,  const float* __restrict__ tf,
     const float* __restrict__ w1, const float* __restrict__ w2,
     const float* __restrict__ wq, const float* __restrict__ wk,
     const float* __restrict__ wv, const float* __restrict__ wo,
     float* __restrict__ out, float* __restrict__ out2){
  __shared__ float sbuf[2176];
  const int bid = blockIdx.x, tid = threadIdx.x;
  const int warp = tid>>5, lane = tid&31;

  // capture gate generations (tid 0 only; used only by tid 0)
  unsigned int base0=0u, base1=0u, base2=0u, base3=0u;
  if (tid==0){ base0=g_gen[0]; base1=g_gen[1]; base2=g_gen[2]; base3=g_gen[3]; }

  // ========== P0: mean/max sweep (840 blocks) || u (4) || q (44) ===========
  if (bid < NSW){
    for (int row = bid*8 + warp; row < BB*CC; row += NSW*8){
      const float4* xr = (const float4*)(x + (size_t)row*HW);
      float s = 0.f, m = -CUDART_INF_F;
      #pragma unroll 2
      for (int i=lane; i<NF4; i+=32){
        float4 v = xr[i];
        s += (v.x+v.y)+(v.z+v.w);
        m = fmaxf(m, fmaxf(fmaxf(v.x,v.y), fmaxf(v.z,v.w)));
      }
      s = warp_sum(s); m = warp_max(m);
      if (lane==0){ d_avg[row] = s*(1.f/(float)HW); d_maxv[row] = m; }
    }
  } else if (bid < NSW+4){
    // u[c] = sum_a wo[a]*wv[a,c]  (4 blocks x 256 c)
    int c = (bid-NSW)*256 + tid;
    float acc = 0.f;
    #pragma unroll 8
    for (int a=0;a<AD;a++) acc += __ldg(wo+a)*wv[a*CC + c];
    d_u[c] = acc;
  } else {
    // q[b,a] = dot(tf[b,:], wq[a,:]); 256 items over 44 blocks
    for (int it = bid-(NSW+4); it < 256; it += 44){
      int chunk = it & 7, b = it >> 3;
      __syncthreads();
      for (int i=tid;i<TD;i+=256) sbuf[i] = tf[b*TD+i];
      __syncthreads();
      int a0 = chunk*32 + warp*4;
      const float* q0 = wq + (size_t)(a0+0)*TD;
      const float* q1 = wq + (size_t)(a0+1)*TD;
      const float* q2 = wq + (size_t)(a0+2)*TD;
      const float* q3 = wq + (size_t)(a0+3)*TD;
      float acc0=0.f,acc1=0.f,acc2=0.f,acc3=0.f;
      #pragma unroll 4
      for (int i=lane;i<TD;i+=32){
        float t = sbuf[i];
        acc0 += q0[i]*t; acc1 += q1[i]*t; acc2 += q2[i]*t; acc3 += q3[i]*t;
      }
      acc0=warp_sum(acc0); acc1=warp_sum(acc1); acc2=warp_sum(acc2); acc3=warp_sum(acc3);
      if (lane==0){
        d_q[b*AD+a0+0]=acc0; d_q[b*AD+a0+1]=acc1;
        d_q[b*AD+a0+2]=acc2; d_q[b*AD+a0+3]=acc3;
      }
    }
  }
  arrive_gate(0, NB);

  if (bid < 512){
    wait_gate(0, base0);

    // ========== P1: hidden MLP (256 blocks) || qk (128 blocks) =============
    if (bid < 384){
      if (bid < 256){
        int b = bid>>3, rch = bid&7;
        for (int i=tid;i<CC;i+=256){ sbuf[i]=d_avg[b*CC+i]; sbuf[1024+i]=d_maxv[b*CC+i]; }
        __syncthreads();
        int r = rch*8 + warp;
        const float* wr = w1 + (size_t)r*CC;
        float a=0.f, m=0.f;
        #pragma unroll 8
        for (int i=lane;i<CC;i+=32){ float wv_=wr[i]; a+=wv_*sbuf[i]; m+=wv_*sbuf[1024+i]; }
        a=warp_sum(a); m=warp_sum(m);
        if (lane==0) d_hs[b*REDU+r] = fmaxf(a,0.f)+fmaxf(m,0.f);
      } else {
        int idx = bid-256, b = idx>>2, cch = idx&3;
        if (tid < AD) sbuf[tid] = d_q[b*AD+tid];
        __syncthreads();
        int c = cch*256 + tid;
        float qk = 0.f;
        #pragma unroll 8
        for (int a=0;a<AD;a++) qk += sbuf[a]*wk[a*CC + c];
        d_qk[b*CC+c] = qk;
      }
      arrive_gate(1, 384);
    }
    wait_gate(1, base1);

    // ========== P3: inline chattn + dual contraction (512 blocks) ==========
    {
      int chunk = bid & (NCH-1), b = bid >> 4;
      int c0 = chunk*NCHC;
      if (tid < REDU) sbuf[tid] = d_hs[b*REDU+tid];
      __syncthreads();
      if (tid < NCHC){
        int c = c0 + tid;
        const float4* w2v = (const float4*)(w2 + (size_t)c*REDU);
        float acc = 0.f;
        #pragma unroll
        for (int r4=0;r4<REDU/4;r4++){
          float4 wv4 = w2v[r4];
          acc += wv4.x*sbuf[r4*4+0] + wv4.y*sbuf[r4*4+1]
               + wv4.z*sbuf[r4*4+2] + wv4.w*sbuf[r4*4+3];
        }
        float ch = 1.f/(1.f+__expf(-acc));
        d_chattn[b*CC+c] = ch;
        sbuf[64+tid]  = d_qk[b*CC+c] * ch * 0.0625f;  // g
        sbuf[128+tid] = d_u[c] * ch;                  // h
      }
      __syncthreads();
      if (tid < NF4){
        const float4* xb4 = (const float4*)(x + ((size_t)b*CC + c0)*HW);
        float4 aS = make_float4(0.f,0.f,0.f,0.f);
        float4 aY = make_float4(0.f,0.f,0.f,0.f);
        #pragma unroll 8
        for (int c=0;c<NCHC;c++){
          float4 v = xb4[c*NF4 + tid];
          float gc = sbuf[64+c], hc = sbuf[128+c];
          aS.x += gc*v.x; aS.y += gc*v.y; aS.z += gc*v.z; aS.w += gc*v.w;
          aY.x += hc*v.x; aY.y += hc*v.y; aY.z += hc*v.z; aY.w += hc*v.w;
        }
        ((float4*)(d_pS + ((size_t)b*NCH + chunk)*HW))[tid] = aS;
        ((float4*)(d_pY + ((size_t)b*NCH + chunk)*HW))[tid] = aY;
      }
    }
    arrive_gate(2, 512);

    // ========== P4: softmax collapse -> s[b]; out2 (32 blocks) =============
    if (bid < BB){
      wait_gate(2, base2);
      int b = bid;
      const float* pS = d_pS + (size_t)b*NCH*HW;
      const float* pY = d_pY + (size_t)b*NCH*HW;
      bool has4 = tid < (HW - 768);   // tid < 16
      float sc0=0.f,sc1=0.f,sc2=0.f,sc3=0.f, y0=0.f,y1=0.f,y2=0.f,y3=0.f;
      #pragma unroll
      for (int k=0;k<NCH;k++){
        const float* ps = pS + k*HW + tid;
        const float* py = pY + k*HW + tid;
        sc0 += ps[0]; sc1 += ps[256]; sc2 += ps[512]; if (has4) sc3 += ps[768];
        y0  += py[0]; y1  += py[256]; y2  += py[512]; if (has4) y3  += py[768];
      }
      float m = fmaxf(fmaxf(sc0,sc1),sc2); if (has4) m = fmaxf(m,sc3);
      m = warp_max(m);
      if (lane==0) sbuf[warp]=m;
      __syncthreads();
      if (tid==0){ float mm=sbuf[0]; for(int i=1;i<8;i++) mm=fmaxf(mm,sbuf[i]); sbuf[32]=mm; }
      __syncthreads();
      float mm = sbuf[32];
      float e0=__expf(sc0-mm), e1=__expf(sc1-mm), e2=__expf(sc2-mm);
      float e3 = has4 ? __expf(sc3-mm) : 0.f;
      float se  = (e0+e1)+(e2+e3);
      float sey = (e0*y0+e1*y1)+(e2*y2+e3*y3);
      se = warp_sum(se); sey = warp_sum(sey);
      __syncthreads();
      if (lane==0){ sbuf[warp]=se; sbuf[8+warp]=sey; }
      __syncthreads();
      if (tid==0){
        float te=0.f, tey=0.f;
        for(int i=0;i<8;i++){ te+=sbuf[i]; tey+=sbuf[8+i]; }
        float sv = 1.f/(1.f+__expf(-tey/te));
        d_s[b]=sv; sbuf[33]=sv;
      }
      __syncthreads();
      if (out2){
        float sv = sbuf[33];
        for (int n=tid;n<HW;n+=256) out2[b*HW+n] = sv;
      }
      arrive_gate(3, 32);
    }
    wait_gate(3, base3);
  } else {
    // blocks 512..887: nothing to do until s/chattn are final
    wait_gate(3, base3);
  }

  // ========== P5: output sweep (all blocks) ================================
  for (int row = bid*8 + warp; row < BB*CC; row += NB*8){
    float scale = d_chattn[row]*d_s[row>>10];
    const float4* xr = (const float4*)(x + (size_t)row*HW);
    float4* orow = (float4*)(out + (size_t)row*HW);
    #pragma unroll 2
    for (int i=lane;i<NF4;i+=32){
      float4 v = xr[i];
      v.x*=scale; v.y*=scale; v.z*=scale; v.w*=scale;
      orow[i] = v;
    }
  }
}

extern "C" void kernel_launch(void* const* d_in, const int* in_sizes, int n_in,
                              void* d_out, int out_size){
  const float* x  = (const float*)d_in[0];
  const float* tf = (const float*)d_in[1];
  const float* w1 = (const float*)d_in[2];
  const float* w2 = (const float*)d_in[3];
  const float* wq = (const float*)d_in[4];
  const float* wk = (const float*)d_in[5];
  const float* wv = (const float*)d_in[6];
  const float* wo = (const float*)d_in[7];
  float* out = (float*)d_out;
  long long main_elems = (long long)BB*CC*HW;
  float* out2 = ((long long)out_size >= main_elems + (long long)BB*HW)
                  ? out + main_elems : nullptr;

  mega<<<NB, 256>>>(x, tf, w1, w2, wq, wk, wv, wo, out, out2);
}

// round 14
// speedup vs baseline: 1.1149x; 1.1149x over previous
#include <cuda_runtime.h>
#include <math_constants.h>

#define BB 32
#define CC 1024
#define HW 784
#define NF4 196          // HW/4
#define REDU 64
#define TD 768
#define AD 256
#define NCH 16           // chunks for contraction: 64 channels each
#define NCHC 64          // CC/NCH
#define NBM 512          // mid-kernel blocks (single wave, 4/SM safe)

// ---- scratch (device globals; no allocation allowed) ----
__device__ float d_avg[BB*CC];
__device__ float d_maxv[BB*CC];
__device__ float d_chattn[BB*CC];
__device__ float d_qk[BB*CC];
__device__ float d_hs[BB*REDU];
__device__ float d_q[BB*AD];
__device__ float d_u[CC];
__device__ float d_pS[BB*NCH*HW];
__device__ float d_pY[BB*NCH*HW];
__device__ float d_s[BB];
__device__ unsigned int g_cnt[2];
__device__ volatile unsigned int g_gen[2];

__device__ __forceinline__ float warp_sum(float v){
  #pragma unroll
  for (int o=16;o;o>>=1) v += __shfl_xor_sync(0xffffffffu, v, o);
  return v;
}
__device__ __forceinline__ float warp_max(float v){
  #pragma unroll
  for (int o=16;o;o>>=1) v = fmaxf(v, __shfl_xor_sync(0xffffffffu, v, o));
  return v;
}

__device__ __forceinline__ void arrive_gate(int i, unsigned int tgt){
  __threadfence();
  __syncthreads();
  if (threadIdx.x==0){
    if (atomicAdd(&g_cnt[i],1u) == tgt-1u){
      g_cnt[i] = 0u;
      __threadfence();
      g_gen[i] = g_gen[i] + 1u;   // release
    }
  }
}
__device__ __forceinline__ void wait_gate(int i, unsigned int base){
  if (threadIdx.x==0){
    while (g_gen[i] == base) {}   // volatile spin
    __threadfence();              // acquire
  }
  __syncthreads();
}

// ---------------------------------------------------------------------------
// kFront: blocks [0,4096): mean/max warp-per-row (exact, no loop).
//         [4096,4100): u = wo@wv.  [4100,4356): q items.
// ---------------------------------------------------------------------------
__global__ void kFront(const float* __restrict__ x,
                       const float* __restrict__ wv, const float* __restrict__ wo,
                       const float* __restrict__ tf, const float* __restrict__ wq){
  __shared__ float sh[TD];
  int bid = blockIdx.x, tid = threadIdx.x;
  int warp = tid>>5, lane = tid&31;
  if (bid < 4096){
    int row = bid*8 + warp;
    const float4* xr = (const float4*)(x + (size_t)row*HW);
    float s = 0.f, m = -CUDART_INF_F;
    #pragma unroll 2
    for (int i=lane; i<NF4; i+=32){
      float4 v = xr[i];
      s += (v.x+v.y)+(v.z+v.w);
      m = fmaxf(m, fmaxf(fmaxf(v.x,v.y), fmaxf(v.z,v.w)));
    }
    s = warp_sum(s); m = warp_max(m);
    if (lane==0){ d_avg[row] = s*(1.f/(float)HW); d_maxv[row] = m; }
  } else if (bid < 4100){
    int c = (bid-4096)*256 + tid;
    float acc = 0.f;
    #pragma unroll 8
    for (int a=0;a<AD;a++) acc += __ldg(wo+a)*wv[a*CC + c];
    d_u[c] = acc;
  } else {
    int it = bid - 4100;             // 0..255
    int chunk = it & 7, b = it >> 3;
    for (int i=tid;i<TD;i+=256) sh[i] = tf[b*TD+i];
    __syncthreads();
    int a0 = chunk*32 + warp*4;
    const float* q0 = wq + (size_t)(a0+0)*TD;
    const float* q1 = wq + (size_t)(a0+1)*TD;
    const float* q2 = wq + (size_t)(a0+2)*TD;
    const float* q3 = wq + (size_t)(a0+3)*TD;
    float acc0=0.f,acc1=0.f,acc2=0.f,acc3=0.f;
    #pragma unroll 4
    for (int i=lane;i<TD;i+=32){
      float t = sh[i];
      acc0 += q0[i]*t; acc1 += q1[i]*t; acc2 += q2[i]*t; acc3 += q3[i]*t;
    }
    acc0=warp_sum(acc0); acc1=warp_sum(acc1); acc2=warp_sum(acc2); acc3=warp_sum(acc3);
    if (lane==0){
      d_q[b*AD+a0+0]=acc0; d_q[b*AD+a0+1]=acc1;
      d_q[b*AD+a0+2]=acc2; d_q[b*AD+a0+3]=acc3;
    }
  }
}

// ---------------------------------------------------------------------------
// kMid: P1 (MLP 256 blocks || qk 128 blocks) -> gate0 -> P3 (512 blocks)
//       -> gate1 -> P4 (32 blocks). Non-participants exit early.
// ---------------------------------------------------------------------------
__global__ void __launch_bounds__(256, 4)
kMid(const float* __restrict__ x,  const float* __restrict__ w1,
     const float* __restrict__ w2, const float* __restrict__ wk,
     float* __restrict__ out2){
  __shared__ float sbuf[2176];
  const int bid = blockIdx.x, tid = threadIdx.x;
  const int warp = tid>>5, lane = tid&31;
  unsigned int base0=0u, base1=0u;
  if (tid==0){ base0=g_gen[0]; base1=g_gen[1]; }

  // ---- P1 ----
  if (bid < 384){
    if (bid < 256){
      int b = bid>>3, rch = bid&7;
      for (int i=tid;i<CC;i+=256){ sbuf[i]=d_avg[b*CC+i]; sbuf[1024+i]=d_maxv[b*CC+i]; }
      __syncthreads();
      int r = rch*8 + warp;
      const float* wr = w1 + (size_t)r*CC;
      float a=0.f, m=0.f;
      #pragma unroll 8
      for (int i=lane;i<CC;i+=32){ float wv_=wr[i]; a+=wv_*sbuf[i]; m+=wv_*sbuf[1024+i]; }
      a=warp_sum(a); m=warp_sum(m);
      if (lane==0) d_hs[b*REDU+r] = fmaxf(a,0.f)+fmaxf(m,0.f);
    } else {
      int idx = bid-256, b = idx>>2, cch = idx&3;
      if (tid < AD) sbuf[tid] = d_q[b*AD+tid];
      __syncthreads();
      int c = cch*256 + tid;
      float qk = 0.f;
      #pragma unroll 8
      for (int a=0;a<AD;a++) qk += sbuf[a]*wk[a*CC + c];
      d_qk[b*CC+c] = qk;
    }
    arrive_gate(0, 384);
  }
  wait_gate(0, base0);

  // ---- P3: inline chattn + dual contraction ----
  {
    int chunk = bid & (NCH-1), b = bid >> 4;
    int c0 = chunk*NCHC;
    if (tid < REDU) sbuf[tid] = d_hs[b*REDU+tid];
    __syncthreads();
    if (tid < NCHC){
      int c = c0 + tid;
      const float4* w2v = (const float4*)(w2 + (size_t)c*REDU);
      float acc = 0.f;
      #pragma unroll
      for (int r4=0;r4<REDU/4;r4++){
        float4 wv4 = w2v[r4];
        acc += wv4.x*sbuf[r4*4+0] + wv4.y*sbuf[r4*4+1]
             + wv4.z*sbuf[r4*4+2] + wv4.w*sbuf[r4*4+3];
      }
      float ch = 1.f/(1.f+__expf(-acc));
      d_chattn[b*CC+c] = ch;
      sbuf[64+tid]  = d_qk[b*CC+c] * ch * 0.0625f;  // g
      sbuf[128+tid] = d_u[c] * ch;                  // h
    }
    __syncthreads();
    if (tid < NF4){
      const float4* xb4 = (const float4*)(x + ((size_t)b*CC + c0)*HW);
      float4 aS = make_float4(0.f,0.f,0.f,0.f);
      float4 aY = make_float4(0.f,0.f,0.f,0.f);
      #pragma unroll 8
      for (int c=0;c<NCHC;c++){
        float4 v = xb4[c*NF4 + tid];
        float gc = sbuf[64+c], hc = sbuf[128+c];
        aS.x += gc*v.x; aS.y += gc*v.y; aS.z += gc*v.z; aS.w += gc*v.w;
        aY.x += hc*v.x; aY.y += hc*v.y; aY.z += hc*v.z; aY.w += hc*v.w;
      }
      ((float4*)(d_pS + ((size_t)b*NCH + chunk)*HW))[tid] = aS;
      ((float4*)(d_pY + ((size_t)b*NCH + chunk)*HW))[tid] = aY;
    }
  }
  arrive_gate(1, NBM);
  if (bid >= BB) return;          // only P4 blocks continue
  wait_gate(1, base1);

  // ---- P4: softmax collapse -> s[b]; out2 ----
  {
    int b = bid;
    const float* pS = d_pS + (size_t)b*NCH*HW;
    const float* pY = d_pY + (size_t)b*NCH*HW;
    bool has4 = tid < (HW - 768);   // tid < 16
    float sc0=0.f,sc1=0.f,sc2=0.f,sc3=0.f, y0=0.f,y1=0.f,y2=0.f,y3=0.f;
    #pragma unroll
    for (int k=0;k<NCH;k++){
      const float* ps = pS + k*HW + tid;
      const float* py = pY + k*HW + tid;
      sc0 += ps[0]; sc1 += ps[256]; sc2 += ps[512]; if (has4) sc3 += ps[768];
      y0  += py[0]; y1  += py[256]; y2  += py[512]; if (has4) y3  += py[768];
    }
    float m = fmaxf(fmaxf(sc0,sc1),sc2); if (has4) m = fmaxf(m,sc3);
    m = warp_max(m);
    if (lane==0) sbuf[warp]=m;
    __syncthreads();
    if (tid==0){ float mm=sbuf[0]; for(int i=1;i<8;i++) mm=fmaxf(mm,sbuf[i]); sbuf[32]=mm; }
    __syncthreads();
    float mm = sbuf[32];
    float e0=__expf(sc0-mm), e1=__expf(sc1-mm), e2=__expf(sc2-mm);
    float e3 = has4 ? __expf(sc3-mm) : 0.f;
    float se  = (e0+e1)+(e2+e3);
    float sey = (e0*y0+e1*y1)+(e2*y2+e3*y3);
    se = warp_sum(se); sey = warp_sum(sey);
    __syncthreads();
    if (lane==0){ sbuf[warp]=se; sbuf[8+warp]=sey; }
    __syncthreads();
    if (tid==0){
      float te=0.f, tey=0.f;
      for(int i=0;i<8;i++){ te+=sbuf[i]; tey+=sbuf[8+i]; }
      float sv = 1.f/(1.f+__expf(-tey/te));
      d_s[b]=sv; sbuf[33]=sv;
    }
    __syncthreads();
    if (out2){
      float sv = sbuf[33];
      for (int n=tid;n<HW;n+=256) out2[b*HW+n] = sv;
    }
  }
}

// ---------------------------------------------------------------------------
// kBack: blocks [0,4096): out = x*chattn*s, warp-per-row (exact).
// ---------------------------------------------------------------------------
__global__ void kBack(const float* __restrict__ x, float* __restrict__ out){
  int warp=threadIdx.x>>5, lane=threadIdx.x&31;
  int row = blockIdx.x*8 + warp;
  float scale = d_chattn[row]*d_s[row>>10];
  const float4* xr=(const float4*)(x+(size_t)row*HW);
  float4* orow=(float4*)(out+(size_t)row*HW);
  #pragma unroll 2
  for (int i=lane;i<NF4;i+=32){
    float4 v=xr[i];
    v.x*=scale; v.y*=scale; v.z*=scale; v.w*=scale;
    orow[i]=v;
  }
}

extern "C" void kernel_launch(void* const* d_in, const int* in_sizes, int n_in,
                              void* d_out, int out_size){
  const float* x  = (const float*)d_in[0];
  const float* tf = (const float*)d_in[1];
  const float* w1 = (const float*)d_in[2];
  const float* w2 = (const float*)d_in[3];
  const float* wq = (const float*)d_in[4];
  const float* wk = (const float*)d_in[5];
  const float* wv = (const float*)d_in[6];
  const float* wo = (const float*)d_in[7];
  float* out = (float*)d_out;
  long long main_elems = (long long)BB*CC*HW;
  float* out2 = ((long long)out_size >= main_elems + (long long)BB*HW)
                  ? out + main_elems : nullptr;

  kFront<<<4356, 256>>>(x, wv, wo, tf, wq);
  kMid  <<<NBM, 256>>>(x, w1, w2, wk, out2);
  kBack <<<4096, 256>>>(x, out);
}

// round 15
// speedup vs baseline: 1.2008x; 1.0771x over previous
#include <cuda_runtime.h>
#include <math_constants.h>

#define BB 32
#define CC 1024
#define HW 784
#define NF4 196          // HW/4
#define REDU 64
#define TD 768
#define AD 256
#define NCH 16           // chunks for contraction: 64 channels each
#define NCHC 64          // CC/NCH
#define NBM 512          // mid-kernel blocks (single wave, 4/SM safe)
#define NSIDE 260        // side-work blocks at FRONT of kFront grid

// ---- scratch (device globals; no allocation allowed) ----
__device__ float d_avg[BB*CC];
__device__ float d_maxv[BB*CC];
__device__ float d_chattn[BB*CC];
__device__ float d_qk[BB*CC];
__device__ float d_hs[BB*REDU];
__device__ float d_q[BB*AD];
__device__ float d_u[CC];
__device__ float d_pS[BB*NCH*HW];
__device__ float d_pY[BB*NCH*HW];
__device__ float d_s[BB];
__device__ unsigned int g_cnt[2];
__device__ volatile unsigned int g_gen[2];

__device__ __forceinline__ float warp_sum(float v){
  #pragma unroll
  for (int o=16;o;o>>=1) v += __shfl_xor_sync(0xffffffffu, v, o);
  return v;
}
__device__ __forceinline__ float warp_max(float v){
  #pragma unroll
  for (int o=16;o;o>>=1) v = fmaxf(v, __shfl_xor_sync(0xffffffffu, v, o));
  return v;
}

__device__ __forceinline__ void arrive_gate(int i, unsigned int tgt){
  __threadfence();
  __syncthreads();
  if (threadIdx.x==0){
    if (atomicAdd(&g_cnt[i],1u) == tgt-1u){
      g_cnt[i] = 0u;
      __threadfence();
      g_gen[i] = g_gen[i] + 1u;   // release
    }
  }
}
__device__ __forceinline__ void wait_gate(int i, unsigned int base){
  if (threadIdx.x==0){
    while (g_gen[i] == base) {}   // volatile spin
    __threadfence();              // acquire
  }
  __syncthreads();
}

// ---------------------------------------------------------------------------
// kFront: bids [0,4): u = wo@wv.  [4,260): q items (wave-1, hides under sweep).
//         [260,4356): mean/max warp-per-row sweep.
// ---------------------------------------------------------------------------
__global__ void kFront(const float* __restrict__ x,
                       const float* __restrict__ wv, const float* __restrict__ wo,
                       const float* __restrict__ tf, const float* __restrict__ wq){
  __shared__ float sh[TD];
  int bid = blockIdx.x, tid = threadIdx.x;
  int warp = tid>>5, lane = tid&31;
  if (bid >= NSIDE){
    int row = (bid-NSIDE)*8 + warp;
    const float4* xr = (const float4*)(x + (size_t)row*HW);
    float s = 0.f, m = -CUDART_INF_F;
    #pragma unroll 2
    for (int i=lane; i<NF4; i+=32){
      float4 v = xr[i];
      s += (v.x+v.y)+(v.z+v.w);
      m = fmaxf(m, fmaxf(fmaxf(v.x,v.y), fmaxf(v.z,v.w)));
    }
    s = warp_sum(s); m = warp_max(m);
    if (lane==0){ d_avg[row] = s*(1.f/(float)HW); d_maxv[row] = m; }
  } else if (bid < 4){
    int c = bid*256 + tid;
    float acc = 0.f;
    #pragma unroll 8
    for (int a=0;a<AD;a++) acc += __ldg(wo+a)*wv[a*CC + c];
    d_u[c] = acc;
  } else {
    int it = bid - 4;                // 0..255
    int chunk = it & 7, b = it >> 3;
    for (int i=tid;i<TD;i+=256) sh[i] = tf[b*TD+i];
    __syncthreads();
    int a0 = chunk*32 + warp*4;
    const float* q0 = wq + (size_t)(a0+0)*TD;
    const float* q1 = wq + (size_t)(a0+1)*TD;
    const float* q2 = wq + (size_t)(a0+2)*TD;
    const float* q3 = wq + (size_t)(a0+3)*TD;
    float acc0=0.f,acc1=0.f,acc2=0.f,acc3=0.f;
    #pragma unroll 4
    for (int i=lane;i<TD;i+=32){
      float t = sh[i];
      acc0 += q0[i]*t; acc1 += q1[i]*t; acc2 += q2[i]*t; acc3 += q3[i]*t;
    }
    acc0=warp_sum(acc0); acc1=warp_sum(acc1); acc2=warp_sum(acc2); acc3=warp_sum(acc3);
    if (lane==0){
      d_q[b*AD+a0+0]=acc0; d_q[b*AD+a0+1]=acc1;
      d_q[b*AD+a0+2]=acc2; d_q[b*AD+a0+3]=acc3;
    }
  }
}

// ---------------------------------------------------------------------------
// kMid: P1 (MLP 256 blocks || qk 128 blocks) -> gate0 -> P3 (512 blocks)
//       -> gate1 -> P4 (32 blocks). Non-participants exit early.
// ---------------------------------------------------------------------------
__global__ void __launch_bounds__(256, 4)
kMid(const float* __restrict__ x,  const float* __restrict__ w1,
     const float* __restrict__ w2, const float* __restrict__ wk,
     float* __restrict__ out2){
  __shared__ float sbuf[2176];
  const int bid = blockIdx.x, tid = threadIdx.x;
  const int warp = tid>>5, lane = tid&31;
  unsigned int base0=0u, base1=0u;
  if (tid==0){ base0=g_gen[0]; base1=g_gen[1]; }

  // ---- P1 ----
  if (bid < 384){
    if (bid < 256){
      int b = bid>>3, rch = bid&7;
      for (int i=tid;i<CC;i+=256){ sbuf[i]=d_avg[b*CC+i]; sbuf[1024+i]=d_maxv[b*CC+i]; }
      __syncthreads();
      int r = rch*8 + warp;
      const float* wr = w1 + (size_t)r*CC;
      float a=0.f, m=0.f;
      #pragma unroll 8
      for (int i=lane;i<CC;i+=32){ float wv_=wr[i]; a+=wv_*sbuf[i]; m+=wv_*sbuf[1024+i]; }
      a=warp_sum(a); m=warp_sum(m);
      if (lane==0) d_hs[b*REDU+r] = fmaxf(a,0.f)+fmaxf(m,0.f);
    } else {
      int idx = bid-256, b = idx>>2, cch = idx&3;
      if (tid < AD) sbuf[tid] = d_q[b*AD+tid];
      __syncthreads();
      int c = cch*256 + tid;
      float qk = 0.f;
      #pragma unroll 8
      for (int a=0;a<AD;a++) qk += sbuf[a]*wk[a*CC + c];
      d_qk[b*CC+c] = qk;
    }
    arrive_gate(0, 384);
  }
  wait_gate(0, base0);

  // ---- P3: inline chattn + dual contraction ----
  {
    int chunk = bid & (NCH-1), b = bid >> 4;
    int c0 = chunk*NCHC;
    if (tid < REDU) sbuf[tid] = d_hs[b*REDU+tid];
    __syncthreads();
    if (tid < NCHC){
      int c = c0 + tid;
      const float4* w2v = (const float4*)(w2 + (size_t)c*REDU);
      float acc = 0.f;
      #pragma unroll
      for (int r4=0;r4<REDU/4;r4++){
        float4 wv4 = w2v[r4];
        acc += wv4.x*sbuf[r4*4+0] + wv4.y*sbuf[r4*4+1]
             + wv4.z*sbuf[r4*4+2] + wv4.w*sbuf[r4*4+3];
      }
      float ch = 1.f/(1.f+__expf(-acc));
      d_chattn[b*CC+c] = ch;
      sbuf[64+tid]  = d_qk[b*CC+c] * ch * 0.0625f;  // g
      sbuf[128+tid] = d_u[c] * ch;                  // h
    }
    __syncthreads();
    if (tid < NF4){
      const float4* xb4 = (const float4*)(x + ((size_t)b*CC + c0)*HW);
      float4 aS = make_float4(0.f,0.f,0.f,0.f);
      float4 aY = make_float4(0.f,0.f,0.f,0.f);
      #pragma unroll 8
      for (int c=0;c<NCHC;c++){
        float4 v = xb4[c*NF4 + tid];
        float gc = sbuf[64+c], hc = sbuf[128+c];
        aS.x += gc*v.x; aS.y += gc*v.y; aS.z += gc*v.z; aS.w += gc*v.w;
        aY.x += hc*v.x; aY.y += hc*v.y; aY.z += hc*v.z; aY.w += hc*v.w;
      }
      ((float4*)(d_pS + ((size_t)b*NCH + chunk)*HW))[tid] = aS;
      ((float4*)(d_pY + ((size_t)b*NCH + chunk)*HW))[tid] = aY;
    }
  }
  arrive_gate(1, NBM);
  if (bid >= BB) return;          // only P4 blocks continue
  wait_gate(1, base1);

  // ---- P4: softmax collapse -> s[b]; out2 ----
  {
    int b = bid;
    const float* pS = d_pS + (size_t)b*NCH*HW;
    const float* pY = d_pY + (size_t)b*NCH*HW;
    bool has4 = tid < (HW - 768);   // tid < 16
    float sc0=0.f,sc1=0.f,sc2=0.f,sc3=0.f, y0=0.f,y1=0.f,y2=0.f,y3=0.f;
    #pragma unroll
    for (int k=0;k<NCH;k++){
      const float* ps = pS + k*HW + tid;
      const float* py = pY + k*HW + tid;
      sc0 += ps[0]; sc1 += ps[256]; sc2 += ps[512]; if (has4) sc3 += ps[768];
      y0  += py[0]; y1  += py[256]; y2  += py[512]; if (has4) y3  += py[768];
    }
    float m = fmaxf(fmaxf(sc0,sc1),sc2); if (has4) m = fmaxf(m,sc3);
    m = warp_max(m);
    if (lane==0) sbuf[warp]=m;
    __syncthreads();
    if (tid==0){ float mm=sbuf[0]; for(int i=1;i<8;i++) mm=fmaxf(mm,sbuf[i]); sbuf[32]=mm; }
    __syncthreads();
    float mm = sbuf[32];
    float e0=__expf(sc0-mm), e1=__expf(sc1-mm), e2=__expf(sc2-mm);
    float e3 = has4 ? __expf(sc3-mm) : 0.f;
    float se  = (e0+e1)+(e2+e3);
    float sey = (e0*y0+e1*y1)+(e2*y2+e3*y3);
    se = warp_sum(se); sey = warp_sum(sey);
    __syncthreads();
    if (lane==0){ sbuf[warp]=se; sbuf[8+warp]=sey; }
    __syncthreads();
    if (tid==0){
      float te=0.f, tey=0.f;
      for(int i=0;i<8;i++){ te+=sbuf[i]; tey+=sbuf[8+i]; }
      float sv = 1.f/(1.f+__expf(-tey/te));
      d_s[b]=sv; sbuf[33]=sv;
    }
    __syncthreads();
    if (out2){
      float sv = sbuf[33];
      for (int n=tid;n<HW;n+=256) out2[b*HW+n] = sv;
    }
  }
}

// ---------------------------------------------------------------------------
// kBack: blocks [0,4096): out = x*chattn*s, warp-per-row (exact).
// ---------------------------------------------------------------------------
__global__ void kBack(const float* __restrict__ x, float* __restrict__ out){
  int warp=threadIdx.x>>5, lane=threadIdx.x&31;
  int row = blockIdx.x*8 + warp;
  float scale = d_chattn[row]*d_s[row>>10];
  const float4* xr=(const float4*)(x+(size_t)row*HW);
  float4* orow=(float4*)(out+(size_t)row*HW);
  #pragma unroll 2
  for (int i=lane;i<NF4;i+=32){
    float4 v=xr[i];
    v.x*=scale; v.y*=scale; v.z*=scale; v.w*=scale;
    orow[i]=v;
  }
}

extern "C" void kernel_launch(void* const* d_in, const int* in_sizes, int n_in,
                              void* d_out, int out_size){
  const float* x  = (const float*)d_in[0];
  const float* tf = (const float*)d_in[1];
  const float* w1 = (const float*)d_in[2];
  const float* w2 = (const float*)d_in[3];
  const float* wq = (const float*)d_in[4];
  const float* wk = (const float*)d_in[5];
  const float* wv = (const float*)d_in[6];
  const float* wo = (const float*)d_in[7];
  float* out = (float*)d_out;
  long long main_elems = (long long)BB*CC*HW;
  float* out2 = ((long long)out_size >= main_elems + (long long)BB*HW)
                  ? out + main_elems : nullptr;

  kFront<<<NSIDE+4096, 256>>>(x, wv, wo, tf, wq);
  kMid  <<<NBM, 256>>>(x, w1, w2, wk, out2);
  kBack <<<4096, 256>>>(x, out);
}